// round 12
// baseline (speedup 1.0000x reference)
#include <cuda_runtime.h>
#include <cuda_fp16.h>
#include <cstdint>

#define B_ 2
#define S_ 2048
#define E_ 768
#define H_ 12
#define D_ 64
#define M_ (B_*S_)
#define PK 40   // proj smem stride (halfs): 80B rows, conflict-free ldmatrix
#define PD 72   // attn smem stride (halfs): 144B rows, conflict-free ldmatrix
#define LOG2E 1.44269504f

// Pre-split fp16 Q/K/V (device globals; no allocations allowed)
__device__ __half g_qhi[(size_t)B_*H_*S_*D_];
__device__ __half g_qlo[(size_t)B_*H_*S_*D_];
__device__ __half g_khi[(size_t)B_*H_*S_*D_];
__device__ __half g_vhi[(size_t)B_*H_*S_*D_];

// ---------------------------------------------------------------------------
// helpers
// ---------------------------------------------------------------------------
__device__ __forceinline__ uint32_t smem_u32(const void* p) {
    return (uint32_t)__cvta_generic_to_shared(p);
}
__device__ __forceinline__ void ldsm4(uint32_t r[4], uint32_t a) {
    asm volatile("ldmatrix.sync.aligned.m8n8.x4.shared.b16 {%0,%1,%2,%3}, [%4];"
                 : "=r"(r[0]), "=r"(r[1]), "=r"(r[2]), "=r"(r[3]) : "r"(a));
}
__device__ __forceinline__ void ldsm4t(uint32_t r[4], uint32_t a) {
    asm volatile("ldmatrix.sync.aligned.m8n8.x4.trans.shared.b16 {%0,%1,%2,%3}, [%4];"
                 : "=r"(r[0]), "=r"(r[1]), "=r"(r[2]), "=r"(r[3]) : "r"(a));
}
__device__ __forceinline__ void mma16816(float4& c, const uint32_t a[4], const uint32_t b[2]) {
    asm volatile(
        "mma.sync.aligned.m16n8k16.row.col.f32.f16.f16.f32 "
        "{%0,%1,%2,%3}, {%4,%5,%6,%7}, {%8,%9}, {%0,%1,%2,%3};"
        : "+f"(c.x), "+f"(c.y), "+f"(c.z), "+f"(c.w)
        : "r"(a[0]), "r"(a[1]), "r"(a[2]), "r"(a[3]), "r"(b[0]), "r"(b[1]));
}
__device__ __forceinline__ float ex2(float x) {
    float r;
    asm("ex2.approx.ftz.f32 %0, %1;" : "=f"(r) : "f"(x));
    return r;
}
__device__ __forceinline__ void split2(float x, float y, uint32_t& hi, uint32_t& lo) {
    __half2 h = __floats2half2_rn(x, y);
    float2 hf = __half22float2(h);
    __half2 l = __floats2half2_rn(x - hf.x, y - hf.y);
    hi = *(uint32_t*)&h;
    lo = *(uint32_t*)&l;
}
__device__ __forceinline__ void cpa16(uint32_t dst, const void* src) {
    asm volatile("cp.async.ca.shared.global [%0], [%1], 16;" :: "r"(dst), "l"(src));
}
#define CP_COMMIT() asm volatile("cp.async.commit_group;")
#define CP_WAIT0()  asm volatile("cp.async.wait_group 0;")

// ---------------------------------------------------------------------------
// Fused projection GEMM, BM=128 BN=64 BK=32, 256 threads (8 warps: 4m x 2n,
// warp tile 32m x 32n). blockIdx.z selects {Q,K,V}. Split-fp16 tensor cores,
// double-buffered dynamic smem, register-prefetched gmem loads.
// W frags via x4 ldmatrix, 64-bit STS in sts_stage.
// Emits pre-split fp16 hi (lo only for Q) in [B,H,S,D]; Q scale = 0.125*log2e.
// ---------------------------------------------------------------------------
__global__ __launch_bounds__(256, 2) void proj_mma(const float* __restrict__ Xq,
                                                   const float* __restrict__ Xk,
                                                   const float* __restrict__ Xv,
                                                   const float* __restrict__ Wq,
                                                   const float* __restrict__ Wk,
                                                   const float* __restrict__ Wv) {
    extern __shared__ __half psm[];
    __half* Xhi = psm;              // [2][128][PK]
    __half* Xlo = psm + 10240;
    __half* Whi = psm + 20480;      // [2][64][PK]
    __half* Wlo = psm + 25600;
    #define XH(buf,row,k) ((buf)*5120 + (row)*PK + (k))
    #define WH(buf,row,k) ((buf)*2560 + (row)*PK + (k))

    const int z = blockIdx.z;
    const float* X = (z == 0) ? Xq : (z == 1) ? Xk : Xv;
    const float* W = (z == 0) ? Wq : (z == 1) ? Wk : Wv;
    __half* ohi = (z == 0) ? g_qhi : (z == 1) ? g_khi : g_vhi;
    __half* olo = (z == 0) ? g_qlo : (__half*)nullptr;
    const float scale = (z == 0) ? 0.125f * LOG2E : 1.0f;

    const int tid  = threadIdx.x;
    const int lane = tid & 31;
    const int wid  = tid >> 5;
    const int wm = wid & 3;        // m offset 32*wm
    const int wn = wid >> 2;       // n offset 32*wn
    const int i0 = blockIdx.y * 128;
    const int o0 = blockIdx.x * 64;
    const int lr = tid >> 3;       // 0..31
    const int lk = tid & 7;        // float4 slot

    float4 xv[4], wv[2];
    auto ldg_stage = [&](int e0) {
        #pragma unroll
        for (int p = 0; p < 4; p++)
            xv[p] = *(const float4*)&X[(size_t)(i0 + lr + p * 32) * E_ + e0 + lk * 4];
        #pragma unroll
        for (int q = 0; q < 2; q++)
            wv[q] = *(const float4*)&W[(size_t)(o0 + lr + q * 32) * E_ + e0 + lk * 4];
    };
    auto sts_stage = [&](int buf) {
        #pragma unroll
        for (int p = 0; p < 4; p++) {
            int row = lr + p * 32;
            uint32_t h0, l0, h1, l1;
            split2(xv[p].x, xv[p].y, h0, l0); split2(xv[p].z, xv[p].w, h1, l1);
            *(uint2*)&Xhi[XH(buf,row,lk*4)] = make_uint2(h0, h1);
            *(uint2*)&Xlo[XH(buf,row,lk*4)] = make_uint2(l0, l1);
        }
        #pragma unroll
        for (int q = 0; q < 2; q++) {
            int row = lr + q * 32;
            uint32_t h0, l0, h1, l1;
            split2(wv[q].x, wv[q].y, h0, l0); split2(wv[q].z, wv[q].w, h1, l1);
            *(uint2*)&Whi[WH(buf,row,lk*4)] = make_uint2(h0, h1);
            *(uint2*)&Wlo[WH(buf,row,lk*4)] = make_uint2(l0, l1);
        }
    };

    float4 c[2][4];
    #pragma unroll
    for (int m = 0; m < 2; m++)
        #pragma unroll
        for (int t = 0; t < 4; t++) c[m][t] = make_float4(0.f, 0.f, 0.f, 0.f);

    ldg_stage(0);
    sts_stage(0);
    __syncthreads();

    for (int it = 0; it < 24; it++) {
        if (it < 23) ldg_stage((it + 1) * 32);
        const int buf = it & 1;
        #pragma unroll
        for (int kc = 0; kc < 2; kc++) {
            uint32_t ahi[2][4], alo[2][4];
            #pragma unroll
            for (int mt = 0; mt < 2; mt++) {
                int arow = wm*32 + mt*16 + (lane & 15);
                int acol = kc*16 + ((lane >> 4) & 1)*8;
                ldsm4(ahi[mt], smem_u32(&Xhi[XH(buf, arow, acol)]));
                ldsm4(alo[mt], smem_u32(&Xlo[XH(buf, arow, acol)]));
            }
            #pragma unroll
            for (int np = 0; np < 2; np++) {
                int brow = wn*32 + np*16 + ((lane >> 4) & 1)*8 + (lane & 7);
                int bcol = kc*16 + ((lane >> 3) & 1)*8;
                uint32_t bhi[4], blo[4];
                ldsm4(bhi, smem_u32(&Whi[WH(buf, brow, bcol)]));
                ldsm4(blo, smem_u32(&Wlo[WH(buf, brow, bcol)]));
                #pragma unroll
                for (int t = 0; t < 2; t++) {
                    int nt = np*2 + t;
                    #pragma unroll
                    for (int mt = 0; mt < 2; mt++) {
                        mma16816(c[mt][nt], ahi[mt], bhi + 2*t);
                        mma16816(c[mt][nt], ahi[mt], blo + 2*t);
                        mma16816(c[mt][nt], alo[mt], bhi + 2*t);
                    }
                }
            }
        }
        if (it < 23) sts_stage(buf ^ 1);
        __syncthreads();
    }

    const int h = blockIdx.x;
    const int g = lane >> 2, cc2 = (lane & 3) * 2;
    #pragma unroll
    for (int mt = 0; mt < 2; mt++) {
        #pragma unroll
        for (int nt = 0; nt < 4; nt++) {
            int d = wn * 32 + nt * 8 + cc2;
            #pragma unroll
            for (int rr = 0; rr < 2; rr++) {
                int ii = i0 + wm * 32 + mt * 16 + g + rr * 8;
                int b0 = ii >> 11, ss = ii & (S_ - 1);
                size_t off = ((size_t)(b0 * H_ + h) * S_ + ss) * D_ + d;
                float p0 = (rr ? c[mt][nt].z : c[mt][nt].x) * scale;
                float p1 = (rr ? c[mt][nt].w : c[mt][nt].y) * scale;
                uint32_t hh, ll;
                split2(p0, p1, hh, ll);
                *(uint32_t*)&ohi[off] = hh;
                if (olo) *(uint32_t*)&olo[off] = ll;
            }
        }
    }
    #undef XH
    #undef WH
}

// ---------------------------------------------------------------------------
// Two-phase attention, m32 warp tiles (R9 structure), now at 5 CTAs/SM:
// smem (45KB x 5 = 225KB) binds occupancy; regs capped at 204 (was 255).
// Block = (b,h) x 64 q rows, 2 warps, each warp owns 32 q rows.
// Phase A: hi-only QK + ex2 -> rowsums. Phase B: split QK, normalized attn
// write (streaming), AV with single-fp16 V, normalized out.
// cp.async double-buffered, ONE sync per tile, x4 ldmatrix throughout.
// ---------------------------------------------------------------------------
__global__ void __launch_bounds__(64, 5) attn_mma2(const int* __restrict__ mask,
                                                   float* __restrict__ out,
                                                   float* __restrict__ attn) {
    extern __shared__ __half sm[];
    __half* KB0 = sm;                         // 64 x PD
    __half* KB1 = sm + 1 * 64 * PD;
    __half* VH0 = sm + 2 * 64 * PD;
    __half* VH1 = sm + 3 * 64 * PD;
    float*  msks = (float*)(sm + 4 * 64 * PD);   // [S_] multiplicative mask

    const int tid  = threadIdx.x;
    const int lane = tid & 31, wid = tid >> 5;   // wid 0..1
    const int g = lane >> 2, cc2 = (lane & 3) * 2;
    const int bh = blockIdx.y;
    const int b  = bh / H_;
    const int h  = bh - b * H_;
    const int s0 = blockIdx.x * 64;
    const int wq = wid * 32;                     // warp q-row base within CTA

    const __half* qh = g_qhi + ((size_t)bh * S_ + s0) * D_;
    const __half* ql = g_qlo + ((size_t)bh * S_ + s0) * D_;
    const __half* kh = g_khi + (size_t)bh * S_ * D_;
    const __half* vhp = g_vhi + (size_t)bh * S_ * D_;

    // whole-row multiplicative mask -> smem (once)
    const int* mrow = mask + b * S_;
    for (int t = tid; t < S_; t += 64) msks[t] = mrow[t] ? 0.f : 1.f;

    // ---- stage Q hi/lo, extract frags (2 m-tiles per warp) ----
    #pragma unroll
    for (int p = 0; p < 8; p++) {
        int c = tid + p * 64;
        int row = c >> 3, col = (c & 7) * 8;
        cpa16(smem_u32(KB0 + row * PD + col), qh + row * 64 + col);
        cpa16(smem_u32(KB1 + row * PD + col), ql + row * 64 + col);
    }
    CP_COMMIT(); CP_WAIT0();
    __syncthreads();
    uint32_t Qhi[2][4][4], Qlo[2][4][4];
    #pragma unroll
    for (int mt = 0; mt < 2; mt++) {
        #pragma unroll
        for (int d = 0; d < 4; d++) {
            int r = wq + mt*16 + (lane & 15);
            int cofs = d*16 + ((lane >> 4) & 1)*8;
            ldsm4(Qhi[mt][d], smem_u32(KB0 + r * PD + cofs));
            ldsm4(Qlo[mt][d], smem_u32(KB1 + r * PD + cofs));
        }
    }
    __syncthreads();

    auto loadK = [&](int kb, __half* dst) {
        const __half* src = kh + (size_t)kb * 64 * 64;
        #pragma unroll
        for (int p = 0; p < 8; p++) {
            int c = tid + p * 64;
            int row = c >> 3, col = (c & 7) * 8;
            cpa16(smem_u32(dst + row * PD + col), src + row * 64 + col);
        }
    };
    auto loadV = [&](int kb, __half* dh) {
        const __half* sh = vhp + (size_t)kb * 64 * 64;
        #pragma unroll
        for (int p = 0; p < 8; p++) {
            int c = tid + p * 64;
            int row = c >> 3, col = (c & 7) * 8;
            cpa16(smem_u32(dh + row * PD + col), sh + row * 64 + col);
        }
    };

    // K ldmatrix address (x4): 16 keys x 16 k-elems per fetch
    const int krow_off = ((lane >> 4) & 1) * 8 + (lane & 7);
    const int kcol_off = ((lane >> 3) & 1) * 8;
    // V ldmatrix address (x4 trans): 16 keys x 16 d-cols per fetch
    const int vrow_off = lane & 15;
    const int vcol_off = ((lane >> 4) & 1) * 8;

    // ================= Phase A: rowsums (hi-only QK) =================
    float rs[2][2] = {{0.f, 0.f}, {0.f, 0.f}};   // [mt][row-half]
    loadK(0, KB0); CP_COMMIT();
    for (int kb = 0; kb < 32; kb++) {
        CP_WAIT0();
        __syncthreads();
        if (kb < 31) { loadK(kb + 1, (kb & 1) ? KB0 : KB1); CP_COMMIT(); }
        __half* KK = (kb & 1) ? KB1 : KB0;
        const float* mt_ = msks + kb * 64;
        #pragma unroll
        for (int nt2 = 0; nt2 < 4; nt2++) {
            float4 sA[2], sB[2];
            #pragma unroll
            for (int mt = 0; mt < 2; mt++) {
                sA[mt] = make_float4(0.f, 0.f, 0.f, 0.f);
                sB[mt] = make_float4(0.f, 0.f, 0.f, 0.f);
            }
            #pragma unroll
            for (int d = 0; d < 4; d++) {
                uint32_t kf[4];
                ldsm4(kf, smem_u32(KK + (nt2*16 + krow_off) * PD + d*16 + kcol_off));
                #pragma unroll
                for (int mt = 0; mt < 2; mt++) {
                    mma16816(sA[mt], Qhi[mt][d], kf);
                    mma16816(sB[mt], Qhi[mt][d], kf + 2);
                }
            }
            float ma = mt_[nt2*16 + cc2],     mb = mt_[nt2*16 + cc2 + 1];
            float mc = mt_[nt2*16 + 8 + cc2], md = mt_[nt2*16 + 8 + cc2 + 1];
            #pragma unroll
            for (int mt = 0; mt < 2; mt++) {
                rs[mt][0] += ma * ex2(sA[mt].x) + mb * ex2(sA[mt].y)
                           + mc * ex2(sB[mt].x) + md * ex2(sB[mt].y);
                rs[mt][1] += ma * ex2(sA[mt].z) + mb * ex2(sA[mt].w)
                           + mc * ex2(sB[mt].z) + md * ex2(sB[mt].w);
            }
        }
    }
    float inv0[2], inv1[2];
    #pragma unroll
    for (int mt = 0; mt < 2; mt++) {
        float a0 = rs[mt][0], a1 = rs[mt][1];
        a0 += __shfl_xor_sync(0xffffffffu, a0, 1);
        a0 += __shfl_xor_sync(0xffffffffu, a0, 2);
        a1 += __shfl_xor_sync(0xffffffffu, a1, 1);
        a1 += __shfl_xor_sync(0xffffffffu, a1, 2);
        inv0[mt] = 1.0f / a0;
        inv1[mt] = 1.0f / a1;
    }

    // ================= Phase B: normalized attn + AV =================
    float4 o[2][8];
    #pragma unroll
    for (int mt = 0; mt < 2; mt++)
        #pragma unroll
        for (int t = 0; t < 8; t++) o[mt][t] = make_float4(0.f, 0.f, 0.f, 0.f);

    loadK(0, KB0); loadV(0, VH0); CP_COMMIT();
    for (int kb = 0; kb < 32; kb++) {
        CP_WAIT0();
        __syncthreads();
        if (kb < 31) {
            loadK(kb + 1, (kb & 1) ? KB0 : KB1);
            loadV(kb + 1, (kb & 1) ? VH0 : VH1);
            CP_COMMIT();
        }
        __half* KK  = (kb & 1) ? KB1 : KB0;
        __half* VVh = (kb & 1) ? VH1 : VH0;
        const float* mt_ = msks + kb * 64;

        uint32_t phi[2][4][4];
        #pragma unroll
        for (int nt2 = 0; nt2 < 4; nt2++) {
            float4 sA[2], sB[2];
            #pragma unroll
            for (int mt = 0; mt < 2; mt++) {
                sA[mt] = make_float4(0.f, 0.f, 0.f, 0.f);
                sB[mt] = make_float4(0.f, 0.f, 0.f, 0.f);
            }
            #pragma unroll
            for (int d = 0; d < 4; d++) {
                uint32_t kf[4];
                ldsm4(kf, smem_u32(KK + (nt2*16 + krow_off) * PD + d*16 + kcol_off));
                #pragma unroll
                for (int mt = 0; mt < 2; mt++) {
                    mma16816(sA[mt], Qhi[mt][d], kf);
                    mma16816(sA[mt], Qlo[mt][d], kf);
                    mma16816(sB[mt], Qhi[mt][d], kf + 2);
                    mma16816(sB[mt], Qlo[mt][d], kf + 2);
                }
            }
            float ma = mt_[nt2*16 + cc2],     mb = mt_[nt2*16 + cc2 + 1];
            float mc = mt_[nt2*16 + 8 + cc2], md = mt_[nt2*16 + 8 + cc2 + 1];
            size_t col = (size_t)kb * 64 + nt2 * 16 + cc2;
            #pragma unroll
            for (int mt = 0; mt < 2; mt++) {
                float p0 = ma * ex2(sA[mt].x), p1 = mb * ex2(sA[mt].y);
                float p2 = ma * ex2(sA[mt].z), p3 = mb * ex2(sA[mt].w);
                float q0 = mc * ex2(sB[mt].x), q1 = md * ex2(sB[mt].y);
                float q2 = mc * ex2(sB[mt].z), q3 = md * ex2(sB[mt].w);

                int srow = s0 + wq + mt * 16 + g;
                float* r0p = &attn[((size_t)bh * S_ + srow) * S_ + col];
                float* r1p = &attn[((size_t)bh * S_ + srow + 8) * S_ + col];
                __stcs((float2*)r0p,       make_float2(p0 * inv0[mt], p1 * inv0[mt]));
                __stcs((float2*)(r0p + 8), make_float2(q0 * inv0[mt], q1 * inv0[mt]));
                __stcs((float2*)r1p,       make_float2(p2 * inv1[mt], p3 * inv1[mt]));
                __stcs((float2*)(r1p + 8), make_float2(q2 * inv1[mt], q3 * inv1[mt]));

                __half2 h01 = __floats2half2_rn(p0, p1);
                __half2 h23 = __floats2half2_rn(p2, p3);
                __half2 g01 = __floats2half2_rn(q0, q1);
                __half2 g23 = __floats2half2_rn(q2, q3);
                phi[mt][nt2][0] = *(uint32_t*)&h01;
                phi[mt][nt2][1] = *(uint32_t*)&h23;
                phi[mt][nt2][2] = *(uint32_t*)&g01;
                phi[mt][nt2][3] = *(uint32_t*)&g23;
            }
        }

        #pragma unroll
        for (int dt2 = 0; dt2 < 4; dt2++) {
            #pragma unroll
            for (int j = 0; j < 4; j++) {
                uint32_t vh[4];
                ldsm4t(vh, smem_u32(VVh + (j*16 + vrow_off) * PD + dt2*16 + vcol_off));
                #pragma unroll
                for (int mt = 0; mt < 2; mt++) {
                    mma16816(o[mt][2*dt2],     phi[mt][j], vh);
                    mma16816(o[mt][2*dt2 + 1], phi[mt][j], vh + 2);
                }
            }
        }
    }

    // ---- finalize ----
    #pragma unroll
    for (int mt = 0; mt < 2; mt++) {
        int srow = s0 + wq + mt * 16 + g;
        #pragma unroll
        for (int dt = 0; dt < 8; dt++) {
            int d = dt * 8 + cc2;
            *(float2*)&out[(((size_t)b * S_ + srow) * H_ + h) * D_ + d] =
                make_float2(o[mt][dt].x * inv0[mt], o[mt][dt].y * inv0[mt]);
            *(float2*)&out[(((size_t)b * S_ + srow + 8) * H_ + h) * D_ + d] =
                make_float2(o[mt][dt].z * inv1[mt], o[mt][dt].w * inv1[mt]);
        }
    }
}

// ---------------------------------------------------------------------------
extern "C" void kernel_launch(void* const* d_in, const int* in_sizes, int n_in,
                              void* d_out, int out_size) {
    (void)in_sizes; (void)n_in; (void)out_size;
    const float* query = (const float*)d_in[0];
    const float* key   = (const float*)d_in[1];
    const float* value = (const float*)d_in[2];
    const int*   mask  = (const int*)d_in[3];
    const float* Wq    = (const float*)d_in[4];
    const float* Wk    = (const float*)d_in[5];
    const float* Wv    = (const float*)d_in[6];

    float* out  = (float*)d_out;                        // attn_output [B,S,E]
    float* attn = out + (size_t)B_ * S_ * E_;           // attn [B,H,S,S]

    int proj_smem = 30720 * (int)sizeof(__half);        // 61440 B
    cudaFuncSetAttribute(proj_mma, cudaFuncAttributeMaxDynamicSharedMemorySize, proj_smem);
    dim3 pgrid(E_ / 64, M_ / 128, 3);
    proj_mma<<<pgrid, 256, proj_smem>>>(query, key, value, Wq, Wk, Wv);

    int smem_bytes = 4 * 64 * PD * (int)sizeof(__half) + S_ * (int)sizeof(float); // 45056
    cudaFuncSetAttribute(attn_mma2, cudaFuncAttributeMaxDynamicSharedMemorySize, smem_bytes);
    attn_mma2<<<dim3(S_ / 64, B_ * H_), 64, smem_bytes>>>(mask, out, attn);
}

// round 13
// speedup vs baseline: 1.3131x; 1.3131x over previous
#include <cuda_runtime.h>
#include <cuda_fp16.h>
#include <cstdint>

#define B_ 2
#define S_ 2048
#define E_ 768
#define H_ 12
#define D_ 64
#define M_ (B_*S_)
#define PK 40   // proj smem stride (halfs): 80B rows, conflict-free ldmatrix
#define PD 72   // attn smem stride (halfs): 144B rows, conflict-free ldmatrix
#define LOG2E 1.44269504f

// Pre-split fp16 Q/K/V (device globals; no allocations allowed)
__device__ __half g_qhi[(size_t)B_*H_*S_*D_];
__device__ __half g_qlo[(size_t)B_*H_*S_*D_];
__device__ __half g_khi[(size_t)B_*H_*S_*D_];
__device__ __half g_vhi[(size_t)B_*H_*S_*D_];

// ---------------------------------------------------------------------------
// helpers
// ---------------------------------------------------------------------------
__device__ __forceinline__ uint32_t smem_u32(const void* p) {
    return (uint32_t)__cvta_generic_to_shared(p);
}
__device__ __forceinline__ void ldsm4(uint32_t r[4], uint32_t a) {
    asm volatile("ldmatrix.sync.aligned.m8n8.x4.shared.b16 {%0,%1,%2,%3}, [%4];"
                 : "=r"(r[0]), "=r"(r[1]), "=r"(r[2]), "=r"(r[3]) : "r"(a));
}
__device__ __forceinline__ void ldsm4t(uint32_t r[4], uint32_t a) {
    asm volatile("ldmatrix.sync.aligned.m8n8.x4.trans.shared.b16 {%0,%1,%2,%3}, [%4];"
                 : "=r"(r[0]), "=r"(r[1]), "=r"(r[2]), "=r"(r[3]) : "r"(a));
}
__device__ __forceinline__ void mma16816(float4& c, const uint32_t a[4], const uint32_t b[2]) {
    asm volatile(
        "mma.sync.aligned.m16n8k16.row.col.f32.f16.f16.f32 "
        "{%0,%1,%2,%3}, {%4,%5,%6,%7}, {%8,%9}, {%0,%1,%2,%3};"
        : "+f"(c.x), "+f"(c.y), "+f"(c.z), "+f"(c.w)
        : "r"(a[0]), "r"(a[1]), "r"(a[2]), "r"(a[3]), "r"(b[0]), "r"(b[1]));
}
__device__ __forceinline__ float ex2(float x) {
    float r;
    asm("ex2.approx.ftz.f32 %0, %1;" : "=f"(r) : "f"(x));
    return r;
}
__device__ __forceinline__ void split2(float x, float y, uint32_t& hi, uint32_t& lo) {
    __half2 h = __floats2half2_rn(x, y);
    float2 hf = __half22float2(h);
    __half2 l = __floats2half2_rn(x - hf.x, y - hf.y);
    hi = *(uint32_t*)&h;
    lo = *(uint32_t*)&l;
}
__device__ __forceinline__ uint32_t cvt2(float x, float y) {
    __half2 h = __floats2half2_rn(x, y);
    return *(uint32_t*)&h;
}
__device__ __forceinline__ void cpa16(uint32_t dst, const void* src) {
    asm volatile("cp.async.ca.shared.global [%0], [%1], 16;" :: "r"(dst), "l"(src));
}
#define CP_COMMIT() asm volatile("cp.async.commit_group;")
#define CP_WAIT0()  asm volatile("cp.async.wait_group 0;")

// ---------------------------------------------------------------------------
// Fused projection GEMM, BM=128 BN=64 BK=32, 256 threads (8 warps: 4m x 2n,
// warp tile 32m x 32n). blockIdx.z selects {Q,K,V}.
// Q (z=0): split-fp16 Markidis (3 mma) — Q-lo is consumed downstream.
// K/V (z>0): PLAIN fp16 mma (1 mma) — outputs are stored hi-only fp16 anyway,
// so output rounding already dominates; input rounding adds ~1e-4 to probs.
// Double-buffered dynamic smem, register-prefetched gmem loads.
// Emits fp16 hi (lo only for Q) in [B,H,S,D]; Q scale = 0.125*log2e.
// ---------------------------------------------------------------------------
__global__ __launch_bounds__(256, 2) void proj_mma(const float* __restrict__ Xq,
                                                   const float* __restrict__ Xk,
                                                   const float* __restrict__ Xv,
                                                   const float* __restrict__ Wq,
                                                   const float* __restrict__ Wk,
                                                   const float* __restrict__ Wv) {
    extern __shared__ __half psm[];
    __half* Xhi = psm;              // [2][128][PK]
    __half* Xlo = psm + 10240;
    __half* Whi = psm + 20480;      // [2][64][PK]
    __half* Wlo = psm + 25600;
    #define XH(buf,row,k) ((buf)*5120 + (row)*PK + (k))
    #define WH(buf,row,k) ((buf)*2560 + (row)*PK + (k))

    const int z = blockIdx.z;
    const float* X = (z == 0) ? Xq : (z == 1) ? Xk : Xv;
    const float* W = (z == 0) ? Wq : (z == 1) ? Wk : Wv;
    __half* ohi = (z == 0) ? g_qhi : (z == 1) ? g_khi : g_vhi;
    __half* olo = (z == 0) ? g_qlo : (__half*)nullptr;
    const float scale = (z == 0) ? 0.125f * LOG2E : 1.0f;

    const int tid  = threadIdx.x;
    const int lane = tid & 31;
    const int wid  = tid >> 5;
    const int wm = wid & 3;        // m offset 32*wm
    const int wn = wid >> 2;       // n offset 32*wn
    const int i0 = blockIdx.y * 128;
    const int o0 = blockIdx.x * 64;
    const int lr = tid >> 3;       // 0..31
    const int lk = tid & 7;        // float4 slot

    float4 xv[4], wv[2];
    auto ldg_stage = [&](int e0) {
        #pragma unroll
        for (int p = 0; p < 4; p++)
            xv[p] = *(const float4*)&X[(size_t)(i0 + lr + p * 32) * E_ + e0 + lk * 4];
        #pragma unroll
        for (int q = 0; q < 2; q++)
            wv[q] = *(const float4*)&W[(size_t)(o0 + lr + q * 32) * E_ + e0 + lk * 4];
    };
    auto sts_split = [&](int buf) {
        #pragma unroll
        for (int p = 0; p < 4; p++) {
            int row = lr + p * 32;
            uint32_t h0, l0, h1, l1;
            split2(xv[p].x, xv[p].y, h0, l0); split2(xv[p].z, xv[p].w, h1, l1);
            *(uint2*)&Xhi[XH(buf,row,lk*4)] = make_uint2(h0, h1);
            *(uint2*)&Xlo[XH(buf,row,lk*4)] = make_uint2(l0, l1);
        }
        #pragma unroll
        for (int q = 0; q < 2; q++) {
            int row = lr + q * 32;
            uint32_t h0, l0, h1, l1;
            split2(wv[q].x, wv[q].y, h0, l0); split2(wv[q].z, wv[q].w, h1, l1);
            *(uint2*)&Whi[WH(buf,row,lk*4)] = make_uint2(h0, h1);
            *(uint2*)&Wlo[WH(buf,row,lk*4)] = make_uint2(l0, l1);
        }
    };
    auto sts_f16 = [&](int buf) {
        #pragma unroll
        for (int p = 0; p < 4; p++) {
            int row = lr + p * 32;
            *(uint2*)&Xhi[XH(buf,row,lk*4)] =
                make_uint2(cvt2(xv[p].x, xv[p].y), cvt2(xv[p].z, xv[p].w));
        }
        #pragma unroll
        for (int q = 0; q < 2; q++) {
            int row = lr + q * 32;
            *(uint2*)&Whi[WH(buf,row,lk*4)] =
                make_uint2(cvt2(wv[q].x, wv[q].y), cvt2(wv[q].z, wv[q].w));
        }
    };

    float4 c[2][4];
    #pragma unroll
    for (int m = 0; m < 2; m++)
        #pragma unroll
        for (int t = 0; t < 4; t++) c[m][t] = make_float4(0.f, 0.f, 0.f, 0.f);

    ldg_stage(0);
    if (z == 0) sts_split(0); else sts_f16(0);
    __syncthreads();

    if (z == 0) {
        // ---- split-fp16 mainloop (Q) ----
        for (int it = 0; it < 24; it++) {
            if (it < 23) ldg_stage((it + 1) * 32);
            const int buf = it & 1;
            #pragma unroll
            for (int kc = 0; kc < 2; kc++) {
                uint32_t ahi[2][4], alo[2][4];
                #pragma unroll
                for (int mt = 0; mt < 2; mt++) {
                    int arow = wm*32 + mt*16 + (lane & 15);
                    int acol = kc*16 + ((lane >> 4) & 1)*8;
                    ldsm4(ahi[mt], smem_u32(&Xhi[XH(buf, arow, acol)]));
                    ldsm4(alo[mt], smem_u32(&Xlo[XH(buf, arow, acol)]));
                }
                #pragma unroll
                for (int np = 0; np < 2; np++) {
                    int brow = wn*32 + np*16 + ((lane >> 4) & 1)*8 + (lane & 7);
                    int bcol = kc*16 + ((lane >> 3) & 1)*8;
                    uint32_t bhi[4], blo[4];
                    ldsm4(bhi, smem_u32(&Whi[WH(buf, brow, bcol)]));
                    ldsm4(blo, smem_u32(&Wlo[WH(buf, brow, bcol)]));
                    #pragma unroll
                    for (int t = 0; t < 2; t++) {
                        int nt = np*2 + t;
                        #pragma unroll
                        for (int mt = 0; mt < 2; mt++) {
                            mma16816(c[mt][nt], ahi[mt], bhi + 2*t);
                            mma16816(c[mt][nt], ahi[mt], blo + 2*t);
                            mma16816(c[mt][nt], alo[mt], bhi + 2*t);
                        }
                    }
                }
            }
            if (it < 23) sts_split(buf ^ 1);
            __syncthreads();
        }
    } else {
        // ---- plain fp16 mainloop (K, V) ----
        for (int it = 0; it < 24; it++) {
            if (it < 23) ldg_stage((it + 1) * 32);
            const int buf = it & 1;
            #pragma unroll
            for (int kc = 0; kc < 2; kc++) {
                uint32_t ahi[2][4];
                #pragma unroll
                for (int mt = 0; mt < 2; mt++) {
                    int arow = wm*32 + mt*16 + (lane & 15);
                    int acol = kc*16 + ((lane >> 4) & 1)*8;
                    ldsm4(ahi[mt], smem_u32(&Xhi[XH(buf, arow, acol)]));
                }
                #pragma unroll
                for (int np = 0; np < 2; np++) {
                    int brow = wn*32 + np*16 + ((lane >> 4) & 1)*8 + (lane & 7);
                    int bcol = kc*16 + ((lane >> 3) & 1)*8;
                    uint32_t bhi[4];
                    ldsm4(bhi, smem_u32(&Whi[WH(buf, brow, bcol)]));
                    #pragma unroll
                    for (int t = 0; t < 2; t++) {
                        int nt = np*2 + t;
                        #pragma unroll
                        for (int mt = 0; mt < 2; mt++)
                            mma16816(c[mt][nt], ahi[mt], bhi + 2*t);
                    }
                }
            }
            if (it < 23) sts_f16(buf ^ 1);
            __syncthreads();
        }
    }

    const int h = blockIdx.x;
    const int g = lane >> 2, cc2 = (lane & 3) * 2;
    #pragma unroll
    for (int mt = 0; mt < 2; mt++) {
        #pragma unroll
        for (int nt = 0; nt < 4; nt++) {
            int d = wn * 32 + nt * 8 + cc2;
            #pragma unroll
            for (int rr = 0; rr < 2; rr++) {
                int ii = i0 + wm * 32 + mt * 16 + g + rr * 8;
                int b0 = ii >> 11, ss = ii & (S_ - 1);
                size_t off = ((size_t)(b0 * H_ + h) * S_ + ss) * D_ + d;
                float p0 = (rr ? c[mt][nt].z : c[mt][nt].x) * scale;
                float p1 = (rr ? c[mt][nt].w : c[mt][nt].y) * scale;
                uint32_t hh, ll;
                split2(p0, p1, hh, ll);
                *(uint32_t*)&ohi[off] = hh;
                if (olo) *(uint32_t*)&olo[off] = ll;
            }
        }
    }
    #undef XH
    #undef WH
}

// ---------------------------------------------------------------------------
// Two-phase attention, m32 warp tiles (R9 structure — best measured, 4 CTA/SM).
// Block = (b,h) x 64 q rows, 2 warps, each warp owns 32 q rows.
// Phase A: hi-only QK + ex2 -> rowsums. Phase B: split QK, normalized attn
// write (streaming), AV with single-fp16 V, normalized out.
// cp.async double-buffered, ONE sync per tile, x4 ldmatrix throughout.
// ---------------------------------------------------------------------------
__global__ void __launch_bounds__(64, 4) attn_mma2(const int* __restrict__ mask,
                                                   float* __restrict__ out,
                                                   float* __restrict__ attn) {
    extern __shared__ __half sm[];
    __half* KB0 = sm;                         // 64 x PD
    __half* KB1 = sm + 1 * 64 * PD;
    __half* VH0 = sm + 2 * 64 * PD;
    __half* VH1 = sm + 3 * 64 * PD;
    float*  msks = (float*)(sm + 4 * 64 * PD);   // [S_] multiplicative mask

    const int tid  = threadIdx.x;
    const int lane = tid & 31, wid = tid >> 5;   // wid 0..1
    const int g = lane >> 2, cc2 = (lane & 3) * 2;
    const int bh = blockIdx.y;
    const int b  = bh / H_;
    const int h  = bh - b * H_;
    const int s0 = blockIdx.x * 64;
    const int wq = wid * 32;                     // warp q-row base within CTA

    const __half* qh = g_qhi + ((size_t)bh * S_ + s0) * D_;
    const __half* ql = g_qlo + ((size_t)bh * S_ + s0) * D_;
    const __half* kh = g_khi + (size_t)bh * S_ * D_;
    const __half* vhp = g_vhi + (size_t)bh * S_ * D_;

    // whole-row multiplicative mask -> smem (once)
    const int* mrow = mask + b * S_;
    for (int t = tid; t < S_; t += 64) msks[t] = mrow[t] ? 0.f : 1.f;

    // ---- stage Q hi/lo, extract frags (2 m-tiles per warp) ----
    #pragma unroll
    for (int p = 0; p < 8; p++) {
        int c = tid + p * 64;
        int row = c >> 3, col = (c & 7) * 8;
        cpa16(smem_u32(KB0 + row * PD + col), qh + row * 64 + col);
        cpa16(smem_u32(KB1 + row * PD + col), ql + row * 64 + col);
    }
    CP_COMMIT(); CP_WAIT0();
    __syncthreads();
    uint32_t Qhi[2][4][4], Qlo[2][4][4];
    #pragma unroll
    for (int mt = 0; mt < 2; mt++) {
        #pragma unroll
        for (int d = 0; d < 4; d++) {
            int r = wq + mt*16 + (lane & 15);
            int cofs = d*16 + ((lane >> 4) & 1)*8;
            ldsm4(Qhi[mt][d], smem_u32(KB0 + r * PD + cofs));
            ldsm4(Qlo[mt][d], smem_u32(KB1 + r * PD + cofs));
        }
    }
    __syncthreads();

    auto loadK = [&](int kb, __half* dst) {
        const __half* src = kh + (size_t)kb * 64 * 64;
        #pragma unroll
        for (int p = 0; p < 8; p++) {
            int c = tid + p * 64;
            int row = c >> 3, col = (c & 7) * 8;
            cpa16(smem_u32(dst + row * PD + col), src + row * 64 + col);
        }
    };
    auto loadV = [&](int kb, __half* dh) {
        const __half* sh = vhp + (size_t)kb * 64 * 64;
        #pragma unroll
        for (int p = 0; p < 8; p++) {
            int c = tid + p * 64;
            int row = c >> 3, col = (c & 7) * 8;
            cpa16(smem_u32(dh + row * PD + col), sh + row * 64 + col);
        }
    };

    // K ldmatrix address (x4): 16 keys x 16 k-elems per fetch
    const int krow_off = ((lane >> 4) & 1) * 8 + (lane & 7);
    const int kcol_off = ((lane >> 3) & 1) * 8;
    // V ldmatrix address (x4 trans): 16 keys x 16 d-cols per fetch
    const int vrow_off = lane & 15;
    const int vcol_off = ((lane >> 4) & 1) * 8;

    // ================= Phase A: rowsums (hi-only QK) =================
    float rs[2][2] = {{0.f, 0.f}, {0.f, 0.f}};   // [mt][row-half]
    loadK(0, KB0); CP_COMMIT();
    for (int kb = 0; kb < 32; kb++) {
        CP_WAIT0();
        __syncthreads();
        if (kb < 31) { loadK(kb + 1, (kb & 1) ? KB0 : KB1); CP_COMMIT(); }
        __half* KK = (kb & 1) ? KB1 : KB0;
        const float* mt_ = msks + kb * 64;
        #pragma unroll
        for (int nt2 = 0; nt2 < 4; nt2++) {
            float4 sA[2], sB[2];
            #pragma unroll
            for (int mt = 0; mt < 2; mt++) {
                sA[mt] = make_float4(0.f, 0.f, 0.f, 0.f);
                sB[mt] = make_float4(0.f, 0.f, 0.f, 0.f);
            }
            #pragma unroll
            for (int d = 0; d < 4; d++) {
                uint32_t kf[4];
                ldsm4(kf, smem_u32(KK + (nt2*16 + krow_off) * PD + d*16 + kcol_off));
                #pragma unroll
                for (int mt = 0; mt < 2; mt++) {
                    mma16816(sA[mt], Qhi[mt][d], kf);
                    mma16816(sB[mt], Qhi[mt][d], kf + 2);
                }
            }
            float ma = mt_[nt2*16 + cc2],     mb = mt_[nt2*16 + cc2 + 1];
            float mc = mt_[nt2*16 + 8 + cc2], md = mt_[nt2*16 + 8 + cc2 + 1];
            #pragma unroll
            for (int mt = 0; mt < 2; mt++) {
                rs[mt][0] += ma * ex2(sA[mt].x) + mb * ex2(sA[mt].y)
                           + mc * ex2(sB[mt].x) + md * ex2(sB[mt].y);
                rs[mt][1] += ma * ex2(sA[mt].z) + mb * ex2(sA[mt].w)
                           + mc * ex2(sB[mt].z) + md * ex2(sB[mt].w);
            }
        }
    }
    float inv0[2], inv1[2];
    #pragma unroll
    for (int mt = 0; mt < 2; mt++) {
        float a0 = rs[mt][0], a1 = rs[mt][1];
        a0 += __shfl_xor_sync(0xffffffffu, a0, 1);
        a0 += __shfl_xor_sync(0xffffffffu, a0, 2);
        a1 += __shfl_xor_sync(0xffffffffu, a1, 1);
        a1 += __shfl_xor_sync(0xffffffffu, a1, 2);
        inv0[mt] = 1.0f / a0;
        inv1[mt] = 1.0f / a1;
    }

    // ================= Phase B: normalized attn + AV =================
    float4 o[2][8];
    #pragma unroll
    for (int mt = 0; mt < 2; mt++)
        #pragma unroll
        for (int t = 0; t < 8; t++) o[mt][t] = make_float4(0.f, 0.f, 0.f, 0.f);

    loadK(0, KB0); loadV(0, VH0); CP_COMMIT();
    for (int kb = 0; kb < 32; kb++) {
        CP_WAIT0();
        __syncthreads();
        if (kb < 31) {
            loadK(kb + 1, (kb & 1) ? KB0 : KB1);
            loadV(kb + 1, (kb & 1) ? VH0 : VH1);
            CP_COMMIT();
        }
        __half* KK  = (kb & 1) ? KB1 : KB0;
        __half* VVh = (kb & 1) ? VH1 : VH0;
        const float* mt_ = msks + kb * 64;

        uint32_t phi[2][4][4];
        #pragma unroll
        for (int nt2 = 0; nt2 < 4; nt2++) {
            float4 sA[2], sB[2];
            #pragma unroll
            for (int mt = 0; mt < 2; mt++) {
                sA[mt] = make_float4(0.f, 0.f, 0.f, 0.f);
                sB[mt] = make_float4(0.f, 0.f, 0.f, 0.f);
            }
            #pragma unroll
            for (int d = 0; d < 4; d++) {
                uint32_t kf[4];
                ldsm4(kf, smem_u32(KK + (nt2*16 + krow_off) * PD + d*16 + kcol_off));
                #pragma unroll
                for (int mt = 0; mt < 2; mt++) {
                    mma16816(sA[mt], Qhi[mt][d], kf);
                    mma16816(sA[mt], Qlo[mt][d], kf);
                    mma16816(sB[mt], Qhi[mt][d], kf + 2);
                    mma16816(sB[mt], Qlo[mt][d], kf + 2);
                }
            }
            float ma = mt_[nt2*16 + cc2],     mb = mt_[nt2*16 + cc2 + 1];
            float mc = mt_[nt2*16 + 8 + cc2], md = mt_[nt2*16 + 8 + cc2 + 1];
            size_t col = (size_t)kb * 64 + nt2 * 16 + cc2;
            #pragma unroll
            for (int mt = 0; mt < 2; mt++) {
                float p0 = ma * ex2(sA[mt].x), p1 = mb * ex2(sA[mt].y);
                float p2 = ma * ex2(sA[mt].z), p3 = mb * ex2(sA[mt].w);
                float q0 = mc * ex2(sB[mt].x), q1 = md * ex2(sB[mt].y);
                float q2 = mc * ex2(sB[mt].z), q3 = md * ex2(sB[mt].w);

                int srow = s0 + wq + mt * 16 + g;
                float* r0p = &attn[((size_t)bh * S_ + srow) * S_ + col];
                float* r1p = &attn[((size_t)bh * S_ + srow + 8) * S_ + col];
                __stcs((float2*)r0p,       make_float2(p0 * inv0[mt], p1 * inv0[mt]));
                __stcs((float2*)(r0p + 8), make_float2(q0 * inv0[mt], q1 * inv0[mt]));
                __stcs((float2*)r1p,       make_float2(p2 * inv1[mt], p3 * inv1[mt]));
                __stcs((float2*)(r1p + 8), make_float2(q2 * inv1[mt], q3 * inv1[mt]));

                __half2 h01 = __floats2half2_rn(p0, p1);
                __half2 h23 = __floats2half2_rn(p2, p3);
                __half2 g01 = __floats2half2_rn(q0, q1);
                __half2 g23 = __floats2half2_rn(q2, q3);
                phi[mt][nt2][0] = *(uint32_t*)&h01;
                phi[mt][nt2][1] = *(uint32_t*)&h23;
                phi[mt][nt2][2] = *(uint32_t*)&g01;
                phi[mt][nt2][3] = *(uint32_t*)&g23;
            }
        }

        #pragma unroll
        for (int dt2 = 0; dt2 < 4; dt2++) {
            #pragma unroll
            for (int j = 0; j < 4; j++) {
                uint32_t vh[4];
                ldsm4t(vh, smem_u32(VVh + (j*16 + vrow_off) * PD + dt2*16 + vcol_off));
                #pragma unroll
                for (int mt = 0; mt < 2; mt++) {
                    mma16816(o[mt][2*dt2],     phi[mt][j], vh);
                    mma16816(o[mt][2*dt2 + 1], phi[mt][j], vh + 2);
                }
            }
        }
    }

    // ---- finalize ----
    #pragma unroll
    for (int mt = 0; mt < 2; mt++) {
        int srow = s0 + wq + mt * 16 + g;
        #pragma unroll
        for (int dt = 0; dt < 8; dt++) {
            int d = dt * 8 + cc2;
            *(float2*)&out[(((size_t)b * S_ + srow) * H_ + h) * D_ + d] =
                make_float2(o[mt][dt].x * inv0[mt], o[mt][dt].y * inv0[mt]);
            *(float2*)&out[(((size_t)b * S_ + srow + 8) * H_ + h) * D_ + d] =
                make_float2(o[mt][dt].z * inv1[mt], o[mt][dt].w * inv1[mt]);
        }
    }
}

// ---------------------------------------------------------------------------
extern "C" void kernel_launch(void* const* d_in, const int* in_sizes, int n_in,
                              void* d_out, int out_size) {
    (void)in_sizes; (void)n_in; (void)out_size;
    const float* query = (const float*)d_in[0];
    const float* key   = (const float*)d_in[1];
    const float* value = (const float*)d_in[2];
    const int*   mask  = (const int*)d_in[3];
    const float* Wq    = (const float*)d_in[4];
    const float* Wk    = (const float*)d_in[5];
    const float* Wv    = (const float*)d_in[6];

    float* out  = (float*)d_out;                        // attn_output [B,S,E]
    float* attn = out + (size_t)B_ * S_ * E_;           // attn [B,H,S,S]

    int proj_smem = 30720 * (int)sizeof(__half);        // 61440 B
    cudaFuncSetAttribute(proj_mma, cudaFuncAttributeMaxDynamicSharedMemorySize, proj_smem);
    dim3 pgrid(E_ / 64, M_ / 128, 3);
    proj_mma<<<pgrid, 256, proj_smem>>>(query, key, value, Wq, Wk, Wv);

    int smem_bytes = 4 * 64 * PD * (int)sizeof(__half) + S_ * (int)sizeof(float); // 45056
    cudaFuncSetAttribute(attn_mma2, cudaFuncAttributeMaxDynamicSharedMemorySize, smem_bytes);
    attn_mma2<<<dim3(S_ / 64, B_ * H_), 64, smem_bytes>>>(mask, out, attn);
}

// round 14
// speedup vs baseline: 1.4155x; 1.0779x over previous
#include <cuda_runtime.h>
#include <cuda_fp16.h>
#include <cstdint>

#define B_ 2
#define S_ 2048
#define E_ 768
#define H_ 12
#define D_ 64
#define M_ (B_*S_)
#define PK 40   // proj smem stride (halfs): 80B rows, conflict-free ldmatrix
#define PD 72   // attn smem stride (halfs): 144B rows, conflict-free ldmatrix
#define LOG2E 1.44269504f

// fp16 Q/K/V (device globals; no allocations allowed)
__device__ __half g_qhi[(size_t)B_*H_*S_*D_];
__device__ __half g_khi[(size_t)B_*H_*S_*D_];
__device__ __half g_vhi[(size_t)B_*H_*S_*D_];

// ---------------------------------------------------------------------------
// helpers
// ---------------------------------------------------------------------------
__device__ __forceinline__ uint32_t smem_u32(const void* p) {
    return (uint32_t)__cvta_generic_to_shared(p);
}
__device__ __forceinline__ void ldsm4(uint32_t r[4], uint32_t a) {
    asm volatile("ldmatrix.sync.aligned.m8n8.x4.shared.b16 {%0,%1,%2,%3}, [%4];"
                 : "=r"(r[0]), "=r"(r[1]), "=r"(r[2]), "=r"(r[3]) : "r"(a));
}
__device__ __forceinline__ void ldsm4t(uint32_t r[4], uint32_t a) {
    asm volatile("ldmatrix.sync.aligned.m8n8.x4.trans.shared.b16 {%0,%1,%2,%3}, [%4];"
                 : "=r"(r[0]), "=r"(r[1]), "=r"(r[2]), "=r"(r[3]) : "r"(a));
}
__device__ __forceinline__ void mma16816(float4& c, const uint32_t a[4], const uint32_t b[2]) {
    asm volatile(
        "mma.sync.aligned.m16n8k16.row.col.f32.f16.f16.f32 "
        "{%0,%1,%2,%3}, {%4,%5,%6,%7}, {%8,%9}, {%0,%1,%2,%3};"
        : "+f"(c.x), "+f"(c.y), "+f"(c.z), "+f"(c.w)
        : "r"(a[0]), "r"(a[1]), "r"(a[2]), "r"(a[3]), "r"(b[0]), "r"(b[1]));
}
__device__ __forceinline__ float ex2(float x) {
    float r;
    asm("ex2.approx.ftz.f32 %0, %1;" : "=f"(r) : "f"(x));
    return r;
}
__device__ __forceinline__ uint32_t cvt2(float x, float y) {
    __half2 h = __floats2half2_rn(x, y);
    return *(uint32_t*)&h;
}
__device__ __forceinline__ void cpa16(uint32_t dst, const void* src) {
    asm volatile("cp.async.ca.shared.global [%0], [%1], 16;" :: "r"(dst), "l"(src));
}
#define CP_COMMIT() asm volatile("cp.async.commit_group;")
#define CP_WAIT0()  asm volatile("cp.async.wait_group 0;")

// ---------------------------------------------------------------------------
// Fused projection GEMM, BM=128 BN=64 BK=32, 256 threads (8 warps: 4m x 2n,
// warp tile 32m x 32n). blockIdx.z selects {Q,K,V}. PLAIN fp16 mma for all
// three (outputs stored fp16; input rounding ~stays within error budget).
// Double-buffered dynamic smem, register-prefetched gmem loads.
// Emits fp16 in [B,H,S,D]; Q scale = 0.125*log2e.
// ---------------------------------------------------------------------------
__global__ __launch_bounds__(256, 2) void proj_mma(const float* __restrict__ Xq,
                                                   const float* __restrict__ Xk,
                                                   const float* __restrict__ Xv,
                                                   const float* __restrict__ Wq,
                                                   const float* __restrict__ Wk,
                                                   const float* __restrict__ Wv) {
    extern __shared__ __half psm[];
    __half* Xhi = psm;              // [2][128][PK]
    __half* Whi = psm + 10240;      // [2][64][PK]
    #define XH(buf,row,k) ((buf)*5120 + (row)*PK + (k))
    #define WH(buf,row,k) ((buf)*2560 + (row)*PK + (k))

    const int z = blockIdx.z;
    const float* X = (z == 0) ? Xq : (z == 1) ? Xk : Xv;
    const float* W = (z == 0) ? Wq : (z == 1) ? Wk : Wv;
    __half* ohi = (z == 0) ? g_qhi : (z == 1) ? g_khi : g_vhi;
    const float scale = (z == 0) ? 0.125f * LOG2E : 1.0f;

    const int tid  = threadIdx.x;
    const int lane = tid & 31;
    const int wid  = tid >> 5;
    const int wm = wid & 3;        // m offset 32*wm
    const int wn = wid >> 2;       // n offset 32*wn
    const int i0 = blockIdx.y * 128;
    const int o0 = blockIdx.x * 64;
    const int lr = tid >> 3;       // 0..31
    const int lk = tid & 7;        // float4 slot

    float4 xv[4], wv[2];
    auto ldg_stage = [&](int e0) {
        #pragma unroll
        for (int p = 0; p < 4; p++)
            xv[p] = *(const float4*)&X[(size_t)(i0 + lr + p * 32) * E_ + e0 + lk * 4];
        #pragma unroll
        for (int q = 0; q < 2; q++)
            wv[q] = *(const float4*)&W[(size_t)(o0 + lr + q * 32) * E_ + e0 + lk * 4];
    };
    auto sts_stage = [&](int buf) {
        #pragma unroll
        for (int p = 0; p < 4; p++) {
            int row = lr + p * 32;
            *(uint2*)&Xhi[XH(buf,row,lk*4)] =
                make_uint2(cvt2(xv[p].x, xv[p].y), cvt2(xv[p].z, xv[p].w));
        }
        #pragma unroll
        for (int q = 0; q < 2; q++) {
            int row = lr + q * 32;
            *(uint2*)&Whi[WH(buf,row,lk*4)] =
                make_uint2(cvt2(wv[q].x, wv[q].y), cvt2(wv[q].z, wv[q].w));
        }
    };

    float4 c[2][4];
    #pragma unroll
    for (int m = 0; m < 2; m++)
        #pragma unroll
        for (int t = 0; t < 4; t++) c[m][t] = make_float4(0.f, 0.f, 0.f, 0.f);

    ldg_stage(0);
    sts_stage(0);
    __syncthreads();

    for (int it = 0; it < 24; it++) {
        if (it < 23) ldg_stage((it + 1) * 32);
        const int buf = it & 1;
        #pragma unroll
        for (int kc = 0; kc < 2; kc++) {
            uint32_t ahi[2][4];
            #pragma unroll
            for (int mt = 0; mt < 2; mt++) {
                int arow = wm*32 + mt*16 + (lane & 15);
                int acol = kc*16 + ((lane >> 4) & 1)*8;
                ldsm4(ahi[mt], smem_u32(&Xhi[XH(buf, arow, acol)]));
            }
            #pragma unroll
            for (int np = 0; np < 2; np++) {
                int brow = wn*32 + np*16 + ((lane >> 4) & 1)*8 + (lane & 7);
                int bcol = kc*16 + ((lane >> 3) & 1)*8;
                uint32_t bhi[4];
                ldsm4(bhi, smem_u32(&Whi[WH(buf, brow, bcol)]));
                #pragma unroll
                for (int t = 0; t < 2; t++) {
                    int nt = np*2 + t;
                    #pragma unroll
                    for (int mt = 0; mt < 2; mt++)
                        mma16816(c[mt][nt], ahi[mt], bhi + 2*t);
                }
            }
        }
        if (it < 23) sts_stage(buf ^ 1);
        __syncthreads();
    }

    const int h = blockIdx.x;
    const int g = lane >> 2, cc2 = (lane & 3) * 2;
    #pragma unroll
    for (int mt = 0; mt < 2; mt++) {
        #pragma unroll
        for (int nt = 0; nt < 4; nt++) {
            int d = wn * 32 + nt * 8 + cc2;
            #pragma unroll
            for (int rr = 0; rr < 2; rr++) {
                int ii = i0 + wm * 32 + mt * 16 + g + rr * 8;
                int b0 = ii >> 11, ss = ii & (S_ - 1);
                size_t off = ((size_t)(b0 * H_ + h) * S_ + ss) * D_ + d;
                float p0 = (rr ? c[mt][nt].z : c[mt][nt].x) * scale;
                float p1 = (rr ? c[mt][nt].w : c[mt][nt].y) * scale;
                *(uint32_t*)&ohi[off] = cvt2(p0, p1);
            }
        }
    }
    #undef XH
    #undef WH
}

// ---------------------------------------------------------------------------
// Two-phase attention, m32 warp tiles, plain-fp16 Q (no lo). Phase A and
// phase B compute IDENTICAL scores -> normalization exactly consistent.
// Block = (b,h) x 64 q rows, 2 warps, each warp owns 32 q rows.
// Phase A: QK + ex2 -> rowsums. Phase B: QK again, normalized attn write
// (streaming), AV with fp16 V, normalized out.
// cp.async double-buffered, ONE sync per tile, x4 ldmatrix throughout.
// ---------------------------------------------------------------------------
__global__ void __launch_bounds__(64, 4) attn_mma2(const int* __restrict__ mask,
                                                   float* __restrict__ out,
                                                   float* __restrict__ attn) {
    extern __shared__ __half sm[];
    __half* KB0 = sm;                         // 64 x PD
    __half* KB1 = sm + 1 * 64 * PD;
    __half* VH0 = sm + 2 * 64 * PD;
    __half* VH1 = sm + 3 * 64 * PD;
    float*  msks = (float*)(sm + 4 * 64 * PD);   // [S_] multiplicative mask

    const int tid  = threadIdx.x;
    const int lane = tid & 31, wid = tid >> 5;   // wid 0..1
    const int g = lane >> 2, cc2 = (lane & 3) * 2;
    const int bh = blockIdx.y;
    const int b  = bh / H_;
    const int h  = bh - b * H_;
    const int s0 = blockIdx.x * 64;
    const int wq = wid * 32;                     // warp q-row base within CTA

    const __half* qh = g_qhi + ((size_t)bh * S_ + s0) * D_;
    const __half* kh = g_khi + (size_t)bh * S_ * D_;
    const __half* vhp = g_vhi + (size_t)bh * S_ * D_;

    // whole-row multiplicative mask -> smem (once)
    const int* mrow = mask + b * S_;
    for (int t = tid; t < S_; t += 64) msks[t] = mrow[t] ? 0.f : 1.f;

    // ---- stage Q, extract frags (2 m-tiles per warp) ----
    #pragma unroll
    for (int p = 0; p < 8; p++) {
        int c = tid + p * 64;
        int row = c >> 3, col = (c & 7) * 8;
        cpa16(smem_u32(KB0 + row * PD + col), qh + row * 64 + col);
    }
    CP_COMMIT(); CP_WAIT0();
    __syncthreads();
    uint32_t Qhi[2][4][4];
    #pragma unroll
    for (int mt = 0; mt < 2; mt++) {
        #pragma unroll
        for (int d = 0; d < 4; d++) {
            int r = wq + mt*16 + (lane & 15);
            int cofs = d*16 + ((lane >> 4) & 1)*8;
            ldsm4(Qhi[mt][d], smem_u32(KB0 + r * PD + cofs));
        }
    }
    __syncthreads();

    auto loadK = [&](int kb, __half* dst) {
        const __half* src = kh + (size_t)kb * 64 * 64;
        #pragma unroll
        for (int p = 0; p < 8; p++) {
            int c = tid + p * 64;
            int row = c >> 3, col = (c & 7) * 8;
            cpa16(smem_u32(dst + row * PD + col), src + row * 64 + col);
        }
    };
    auto loadV = [&](int kb, __half* dh) {
        const __half* sh = vhp + (size_t)kb * 64 * 64;
        #pragma unroll
        for (int p = 0; p < 8; p++) {
            int c = tid + p * 64;
            int row = c >> 3, col = (c & 7) * 8;
            cpa16(smem_u32(dh + row * PD + col), sh + row * 64 + col);
        }
    };

    // K ldmatrix address (x4): 16 keys x 16 k-elems per fetch
    const int krow_off = ((lane >> 4) & 1) * 8 + (lane & 7);
    const int kcol_off = ((lane >> 3) & 1) * 8;
    // V ldmatrix address (x4 trans): 16 keys x 16 d-cols per fetch
    const int vrow_off = lane & 15;
    const int vcol_off = ((lane >> 4) & 1) * 8;

    // ================= Phase A: rowsums =================
    float rs[2][2] = {{0.f, 0.f}, {0.f, 0.f}};   // [mt][row-half]
    loadK(0, KB0); CP_COMMIT();
    for (int kb = 0; kb < 32; kb++) {
        CP_WAIT0();
        __syncthreads();
        if (kb < 31) { loadK(kb + 1, (kb & 1) ? KB0 : KB1); CP_COMMIT(); }
        __half* KK = (kb & 1) ? KB1 : KB0;
        const float* mt_ = msks + kb * 64;
        #pragma unroll
        for (int nt2 = 0; nt2 < 4; nt2++) {
            float4 sA[2], sB[2];
            #pragma unroll
            for (int mt = 0; mt < 2; mt++) {
                sA[mt] = make_float4(0.f, 0.f, 0.f, 0.f);
                sB[mt] = make_float4(0.f, 0.f, 0.f, 0.f);
            }
            #pragma unroll
            for (int d = 0; d < 4; d++) {
                uint32_t kf[4];
                ldsm4(kf, smem_u32(KK + (nt2*16 + krow_off) * PD + d*16 + kcol_off));
                #pragma unroll
                for (int mt = 0; mt < 2; mt++) {
                    mma16816(sA[mt], Qhi[mt][d], kf);
                    mma16816(sB[mt], Qhi[mt][d], kf + 2);
                }
            }
            float ma = mt_[nt2*16 + cc2],     mb = mt_[nt2*16 + cc2 + 1];
            float mc = mt_[nt2*16 + 8 + cc2], md = mt_[nt2*16 + 8 + cc2 + 1];
            #pragma unroll
            for (int mt = 0; mt < 2; mt++) {
                rs[mt][0] += ma * ex2(sA[mt].x) + mb * ex2(sA[mt].y)
                           + mc * ex2(sB[mt].x) + md * ex2(sB[mt].y);
                rs[mt][1] += ma * ex2(sA[mt].z) + mb * ex2(sA[mt].w)
                           + mc * ex2(sB[mt].z) + md * ex2(sB[mt].w);
            }
        }
    }
    float inv0[2], inv1[2];
    #pragma unroll
    for (int mt = 0; mt < 2; mt++) {
        float a0 = rs[mt][0], a1 = rs[mt][1];
        a0 += __shfl_xor_sync(0xffffffffu, a0, 1);
        a0 += __shfl_xor_sync(0xffffffffu, a0, 2);
        a1 += __shfl_xor_sync(0xffffffffu, a1, 1);
        a1 += __shfl_xor_sync(0xffffffffu, a1, 2);
        inv0[mt] = 1.0f / a0;
        inv1[mt] = 1.0f / a1;
    }

    // ================= Phase B: normalized attn + AV =================
    float4 o[2][8];
    #pragma unroll
    for (int mt = 0; mt < 2; mt++)
        #pragma unroll
        for (int t = 0; t < 8; t++) o[mt][t] = make_float4(0.f, 0.f, 0.f, 0.f);

    loadK(0, KB0); loadV(0, VH0); CP_COMMIT();
    for (int kb = 0; kb < 32; kb++) {
        CP_WAIT0();
        __syncthreads();
        if (kb < 31) {
            loadK(kb + 1, (kb & 1) ? KB0 : KB1);
            loadV(kb + 1, (kb & 1) ? VH0 : VH1);
            CP_COMMIT();
        }
        __half* KK  = (kb & 1) ? KB1 : KB0;
        __half* VVh = (kb & 1) ? VH1 : VH0;
        const float* mt_ = msks + kb * 64;

        uint32_t phi[2][4][4];
        #pragma unroll
        for (int nt2 = 0; nt2 < 4; nt2++) {
            float4 sA[2], sB[2];
            #pragma unroll
            for (int mt = 0; mt < 2; mt++) {
                sA[mt] = make_float4(0.f, 0.f, 0.f, 0.f);
                sB[mt] = make_float4(0.f, 0.f, 0.f, 0.f);
            }
            #pragma unroll
            for (int d = 0; d < 4; d++) {
                uint32_t kf[4];
                ldsm4(kf, smem_u32(KK + (nt2*16 + krow_off) * PD + d*16 + kcol_off));
                #pragma unroll
                for (int mt = 0; mt < 2; mt++) {
                    mma16816(sA[mt], Qhi[mt][d], kf);
                    mma16816(sB[mt], Qhi[mt][d], kf + 2);
                }
            }
            float ma = mt_[nt2*16 + cc2],     mb = mt_[nt2*16 + cc2 + 1];
            float mc = mt_[nt2*16 + 8 + cc2], md = mt_[nt2*16 + 8 + cc2 + 1];
            size_t col = (size_t)kb * 64 + nt2 * 16 + cc2;
            #pragma unroll
            for (int mt = 0; mt < 2; mt++) {
                float p0 = ma * ex2(sA[mt].x), p1 = mb * ex2(sA[mt].y);
                float p2 = ma * ex2(sA[mt].z), p3 = mb * ex2(sA[mt].w);
                float q0 = mc * ex2(sB[mt].x), q1 = md * ex2(sB[mt].y);
                float q2 = mc * ex2(sB[mt].z), q3 = md * ex2(sB[mt].w);

                int srow = s0 + wq + mt * 16 + g;
                float* r0p = &attn[((size_t)bh * S_ + srow) * S_ + col];
                float* r1p = &attn[((size_t)bh * S_ + srow + 8) * S_ + col];
                __stcs((float2*)r0p,       make_float2(p0 * inv0[mt], p1 * inv0[mt]));
                __stcs((float2*)(r0p + 8), make_float2(q0 * inv0[mt], q1 * inv0[mt]));
                __stcs((float2*)r1p,       make_float2(p2 * inv1[mt], p3 * inv1[mt]));
                __stcs((float2*)(r1p + 8), make_float2(q2 * inv1[mt], q3 * inv1[mt]));

                phi[mt][nt2][0] = cvt2(p0, p1);
                phi[mt][nt2][1] = cvt2(p2, p3);
                phi[mt][nt2][2] = cvt2(q0, q1);
                phi[mt][nt2][3] = cvt2(q2, q3);
            }
        }

        #pragma unroll
        for (int dt2 = 0; dt2 < 4; dt2++) {
            #pragma unroll
            for (int j = 0; j < 4; j++) {
                uint32_t vh[4];
                ldsm4t(vh, smem_u32(VVh + (j*16 + vrow_off) * PD + dt2*16 + vcol_off));
                #pragma unroll
                for (int mt = 0; mt < 2; mt++) {
                    mma16816(o[mt][2*dt2],     phi[mt][j], vh);
                    mma16816(o[mt][2*dt2 + 1], phi[mt][j], vh + 2);
                }
            }
        }
    }

    // ---- finalize ----
    #pragma unroll
    for (int mt = 0; mt < 2; mt++) {
        int srow = s0 + wq + mt * 16 + g;
        #pragma unroll
        for (int dt = 0; dt < 8; dt++) {
            int d = dt * 8 + cc2;
            *(float2*)&out[(((size_t)b * S_ + srow) * H_ + h) * D_ + d] =
                make_float2(o[mt][dt].x * inv0[mt], o[mt][dt].y * inv0[mt]);
            *(float2*)&out[(((size_t)b * S_ + srow + 8) * H_ + h) * D_ + d] =
                make_float2(o[mt][dt].z * inv1[mt], o[mt][dt].w * inv1[mt]);
        }
    }
}

// ---------------------------------------------------------------------------
extern "C" void kernel_launch(void* const* d_in, const int* in_sizes, int n_in,
                              void* d_out, int out_size) {
    (void)in_sizes; (void)n_in; (void)out_size;
    const float* query = (const float*)d_in[0];
    const float* key   = (const float*)d_in[1];
    const float* value = (const float*)d_in[2];
    const int*   mask  = (const int*)d_in[3];
    const float* Wq    = (const float*)d_in[4];
    const float* Wk    = (const float*)d_in[5];
    const float* Wv    = (const float*)d_in[6];

    float* out  = (float*)d_out;                        // attn_output [B,S,E]
    float* attn = out + (size_t)B_ * S_ * E_;           // attn [B,H,S,S]

    int proj_smem = 15360 * (int)sizeof(__half);        // 30720 B
    cudaFuncSetAttribute(proj_mma, cudaFuncAttributeMaxDynamicSharedMemorySize, proj_smem);
    dim3 pgrid(E_ / 64, M_ / 128, 3);
    proj_mma<<<pgrid, 256, proj_smem>>>(query, key, value, Wq, Wk, Wv);

    int smem_bytes = 4 * 64 * PD * (int)sizeof(__half) + S_ * (int)sizeof(float); // 45056
    cudaFuncSetAttribute(attn_mma2, cudaFuncAttributeMaxDynamicSharedMemorySize, smem_bytes);
    attn_mma2<<<dim3(S_ / 64, B_ * H_), 64, smem_bytes>>>(mask, out, attn);
}

// round 15
// speedup vs baseline: 1.4864x; 1.0501x over previous
#include <cuda_runtime.h>
#include <cuda_fp16.h>
#include <cstdint>

#define B_ 2
#define S_ 2048
#define E_ 768
#define H_ 12
#define D_ 64
#define M_ (B_*S_)
#define PK 40   // proj smem stride (halfs): 80B rows, conflict-free ldmatrix
#define PD 72   // attn smem stride (halfs): 144B rows, conflict-free ldmatrix
#define LOG2E 1.44269504f

// fp16 Q/K/V outputs + fp16 copies of inputs/weights (device globals)
__device__ __half g_qhi[(size_t)B_*H_*S_*D_];
__device__ __half g_khi[(size_t)B_*H_*S_*D_];
__device__ __half g_vhi[(size_t)B_*H_*S_*D_];
__device__ __half g_xq[(size_t)M_*E_];
__device__ __half g_xk[(size_t)M_*E_];
__device__ __half g_xv[(size_t)M_*E_];
__device__ __half g_wq[(size_t)E_*E_];
__device__ __half g_wk[(size_t)E_*E_];
__device__ __half g_wv[(size_t)E_*E_];

// ---------------------------------------------------------------------------
// helpers
// ---------------------------------------------------------------------------
__device__ __forceinline__ uint32_t smem_u32(const void* p) {
    return (uint32_t)__cvta_generic_to_shared(p);
}
__device__ __forceinline__ void ldsm4(uint32_t r[4], uint32_t a) {
    asm volatile("ldmatrix.sync.aligned.m8n8.x4.shared.b16 {%0,%1,%2,%3}, [%4];"
                 : "=r"(r[0]), "=r"(r[1]), "=r"(r[2]), "=r"(r[3]) : "r"(a));
}
__device__ __forceinline__ void ldsm4t(uint32_t r[4], uint32_t a) {
    asm volatile("ldmatrix.sync.aligned.m8n8.x4.trans.shared.b16 {%0,%1,%2,%3}, [%4];"
                 : "=r"(r[0]), "=r"(r[1]), "=r"(r[2]), "=r"(r[3]) : "r"(a));
}
__device__ __forceinline__ void mma16816(float4& c, const uint32_t a[4], const uint32_t b[2]) {
    asm volatile(
        "mma.sync.aligned.m16n8k16.row.col.f32.f16.f16.f32 "
        "{%0,%1,%2,%3}, {%4,%5,%6,%7}, {%8,%9}, {%0,%1,%2,%3};"
        : "+f"(c.x), "+f"(c.y), "+f"(c.z), "+f"(c.w)
        : "r"(a[0]), "r"(a[1]), "r"(a[2]), "r"(a[3]), "r"(b[0]), "r"(b[1]));
}
__device__ __forceinline__ float ex2(float x) {
    float r;
    asm("ex2.approx.ftz.f32 %0, %1;" : "=f"(r) : "f"(x));
    return r;
}
__device__ __forceinline__ uint32_t cvt2(float x, float y) {
    __half2 h = __floats2half2_rn(x, y);
    return *(uint32_t*)&h;
}
__device__ __forceinline__ void cpa16(uint32_t dst, const void* src) {
    asm volatile("cp.async.ca.shared.global [%0], [%1], 16;" :: "r"(dst), "l"(src));
}
#define CP_COMMIT() asm volatile("cp.async.commit_group;")
#define CP_WAIT0()  asm volatile("cp.async.wait_group 0;")

// ---------------------------------------------------------------------------
// One-shot fp32 -> fp16 conversion of inputs and weights.
// blockIdx.y selects tensor: 0..2 = Xq,Xk,Xv (M_*E_), 3..5 = Wq,Wk,Wv (E_*E_).
// ---------------------------------------------------------------------------
__global__ __launch_bounds__(256) void cvt6(const float* __restrict__ xq,
                                            const float* __restrict__ xk,
                                            const float* __restrict__ xv,
                                            const float* __restrict__ wq,
                                            const float* __restrict__ wk,
                                            const float* __restrict__ wv) {
    const int t = blockIdx.y;
    const float* src = (t == 0) ? xq : (t == 1) ? xk : (t == 2) ? xv
                     : (t == 3) ? wq : (t == 4) ? wk : wv;
    __half* dst = (t == 0) ? g_xq : (t == 1) ? g_xk : (t == 2) ? g_xv
                : (t == 3) ? g_wq : (t == 4) ? g_wk : g_wv;
    const int n4 = (t < 3) ? (M_ * E_ / 4) : (E_ * E_ / 4);
    int i = blockIdx.x * 256 + threadIdx.x;
    if (i >= n4) return;
    float4 v = ((const float4*)src)[i];
    ((uint2*)dst)[i] = make_uint2(cvt2(v.x, v.y), cvt2(v.z, v.w));
}

// ---------------------------------------------------------------------------
// Fused projection GEMM, BM=128 BN=64 BK=32, 256 threads (8 warps: 4m x 2n,
// warp tile 32m x 32n). blockIdx.z selects {Q,K,V}. Pure fp16 pipeline:
// cp.async fp16 tiles -> smem -> ldmatrix -> mma. No LDG staging, no cvt,
// no STS in the mainloop. Emits fp16 in [B,H,S,D]; Q scale = 0.125*log2e.
// ---------------------------------------------------------------------------
__global__ __launch_bounds__(256, 2) void proj_mma(int dummy) {
    extern __shared__ __half psm[];
    __half* Xs = psm;               // [2][128][PK]
    __half* Ws = psm + 10240;       // [2][64][PK]
    #define XH(buf,row,k) ((buf)*5120 + (row)*PK + (k))
    #define WH(buf,row,k) ((buf)*2560 + (row)*PK + (k))

    const int z = blockIdx.z;
    const __half* Xg = (z == 0) ? g_xq : (z == 1) ? g_xk : g_xv;
    const __half* Wg = (z == 0) ? g_wq : (z == 1) ? g_wk : g_wv;
    __half* ohi = (z == 0) ? g_qhi : (z == 1) ? g_khi : g_vhi;
    const float scale = (z == 0) ? 0.125f * LOG2E : 1.0f;

    const int tid  = threadIdx.x;
    const int lane = tid & 31;
    const int wid  = tid >> 5;
    const int wm = wid & 3;        // m offset 32*wm
    const int wn = wid >> 2;       // n offset 32*wn
    const int i0 = blockIdx.y * 128;
    const int o0 = blockIdx.x * 64;

    auto load_tiles = [&](int e0, int buf) {
        // X tile: 128 rows x 32 halfs = 512 x 16B chunks; 256 threads x 2
        #pragma unroll
        for (int p = 0; p < 2; p++) {
            int idx = tid + p * 256;
            int row = idx >> 2, ch = idx & 3;
            cpa16(smem_u32(&Xs[XH(buf, row, ch * 8)]),
                  Xg + (size_t)(i0 + row) * E_ + e0 + ch * 8);
        }
        // W tile: 64 rows x 32 halfs = 256 x 16B chunks
        {
            int row = tid >> 2, ch = tid & 3;
            cpa16(smem_u32(&Ws[WH(buf, row, ch * 8)]),
                  Wg + (size_t)(o0 + row) * E_ + e0 + ch * 8);
        }
    };

    float4 c[2][4];
    #pragma unroll
    for (int m = 0; m < 2; m++)
        #pragma unroll
        for (int t = 0; t < 4; t++) c[m][t] = make_float4(0.f, 0.f, 0.f, 0.f);

    load_tiles(0, 0); CP_COMMIT();

    for (int it = 0; it < 24; it++) {
        CP_WAIT0();
        __syncthreads();
        if (it < 23) { load_tiles((it + 1) * 32, (it & 1) ^ 1); CP_COMMIT(); }
        const int buf = it & 1;
        #pragma unroll
        for (int kc = 0; kc < 2; kc++) {
            uint32_t ahi[2][4];
            #pragma unroll
            for (int mt = 0; mt < 2; mt++) {
                int arow = wm*32 + mt*16 + (lane & 15);
                int acol = kc*16 + ((lane >> 4) & 1)*8;
                ldsm4(ahi[mt], smem_u32(&Xs[XH(buf, arow, acol)]));
            }
            #pragma unroll
            for (int np = 0; np < 2; np++) {
                int brow = wn*32 + np*16 + ((lane >> 4) & 1)*8 + (lane & 7);
                int bcol = kc*16 + ((lane >> 3) & 1)*8;
                uint32_t bhi[4];
                ldsm4(bhi, smem_u32(&Ws[WH(buf, brow, bcol)]));
                #pragma unroll
                for (int t = 0; t < 2; t++) {
                    int nt = np*2 + t;
                    #pragma unroll
                    for (int mt = 0; mt < 2; mt++)
                        mma16816(c[mt][nt], ahi[mt], bhi + 2*t);
                }
            }
        }
        __syncthreads();
    }

    const int h = blockIdx.x;
    const int g = lane >> 2, cc2 = (lane & 3) * 2;
    #pragma unroll
    for (int mt = 0; mt < 2; mt++) {
        #pragma unroll
        for (int nt = 0; nt < 4; nt++) {
            int d = wn * 32 + nt * 8 + cc2;
            #pragma unroll
            for (int rr = 0; rr < 2; rr++) {
                int ii = i0 + wm * 32 + mt * 16 + g + rr * 8;
                int b0 = ii >> 11, ss = ii & (S_ - 1);
                size_t off = ((size_t)(b0 * H_ + h) * S_ + ss) * D_ + d;
                float p0 = (rr ? c[mt][nt].z : c[mt][nt].x) * scale;
                float p1 = (rr ? c[mt][nt].w : c[mt][nt].y) * scale;
                *(uint32_t*)&ohi[off] = cvt2(p0, p1);
            }
        }
    }
    #undef XH
    #undef WH
}

// ---------------------------------------------------------------------------
// Two-phase attention (unchanged from R14 best). m32 warp tiles, plain fp16.
// Block = (b,h) x 64 q rows, 2 warps. Phase A: QK + ex2 -> rowsums.
// Phase B: QK again (identical scores), normalized attn write (streaming),
// AV with fp16 V, normalized out. cp.async double-buffered, one sync/tile.
// ---------------------------------------------------------------------------
__global__ void __launch_bounds__(64, 4) attn_mma2(const int* __restrict__ mask,
                                                   float* __restrict__ out,
                                                   float* __restrict__ attn) {
    extern __shared__ __half sm[];
    __half* KB0 = sm;                         // 64 x PD
    __half* KB1 = sm + 1 * 64 * PD;
    __half* VH0 = sm + 2 * 64 * PD;
    __half* VH1 = sm + 3 * 64 * PD;
    float*  msks = (float*)(sm + 4 * 64 * PD);   // [S_] multiplicative mask

    const int tid  = threadIdx.x;
    const int lane = tid & 31, wid = tid >> 5;   // wid 0..1
    const int g = lane >> 2, cc2 = (lane & 3) * 2;
    const int bh = blockIdx.y;
    const int b  = bh / H_;
    const int h  = bh - b * H_;
    const int s0 = blockIdx.x * 64;
    const int wq = wid * 32;                     // warp q-row base within CTA

    const __half* qh = g_qhi + ((size_t)bh * S_ + s0) * D_;
    const __half* kh = g_khi + (size_t)bh * S_ * D_;
    const __half* vhp = g_vhi + (size_t)bh * S_ * D_;

    // whole-row multiplicative mask -> smem (once)
    const int* mrow = mask + b * S_;
    for (int t = tid; t < S_; t += 64) msks[t] = mrow[t] ? 0.f : 1.f;

    // ---- stage Q, extract frags (2 m-tiles per warp) ----
    #pragma unroll
    for (int p = 0; p < 8; p++) {
        int c = tid + p * 64;
        int row = c >> 3, col = (c & 7) * 8;
        cpa16(smem_u32(KB0 + row * PD + col), qh + row * 64 + col);
    }
    CP_COMMIT(); CP_WAIT0();
    __syncthreads();
    uint32_t Qhi[2][4][4];
    #pragma unroll
    for (int mt = 0; mt < 2; mt++) {
        #pragma unroll
        for (int d = 0; d < 4; d++) {
            int r = wq + mt*16 + (lane & 15);
            int cofs = d*16 + ((lane >> 4) & 1)*8;
            ldsm4(Qhi[mt][d], smem_u32(KB0 + r * PD + cofs));
        }
    }
    __syncthreads();

    auto loadK = [&](int kb, __half* dst) {
        const __half* src = kh + (size_t)kb * 64 * 64;
        #pragma unroll
        for (int p = 0; p < 8; p++) {
            int c = tid + p * 64;
            int row = c >> 3, col = (c & 7) * 8;
            cpa16(smem_u32(dst + row * PD + col), src + row * 64 + col);
        }
    };
    auto loadV = [&](int kb, __half* dh) {
        const __half* sh = vhp + (size_t)kb * 64 * 64;
        #pragma unroll
        for (int p = 0; p < 8; p++) {
            int c = tid + p * 64;
            int row = c >> 3, col = (c & 7) * 8;
            cpa16(smem_u32(dh + row * PD + col), sh + row * 64 + col);
        }
    };

    // K ldmatrix address (x4): 16 keys x 16 k-elems per fetch
    const int krow_off = ((lane >> 4) & 1) * 8 + (lane & 7);
    const int kcol_off = ((lane >> 3) & 1) * 8;
    // V ldmatrix address (x4 trans): 16 keys x 16 d-cols per fetch
    const int vrow_off = lane & 15;
    const int vcol_off = ((lane >> 4) & 1) * 8;

    // ================= Phase A: rowsums =================
    float rs[2][2] = {{0.f, 0.f}, {0.f, 0.f}};   // [mt][row-half]
    loadK(0, KB0); CP_COMMIT();
    for (int kb = 0; kb < 32; kb++) {
        CP_WAIT0();
        __syncthreads();
        if (kb < 31) { loadK(kb + 1, (kb & 1) ? KB0 : KB1); CP_COMMIT(); }
        __half* KK = (kb & 1) ? KB1 : KB0;
        const float* mt_ = msks + kb * 64;
        #pragma unroll
        for (int nt2 = 0; nt2 < 4; nt2++) {
            float4 sA[2], sB[2];
            #pragma unroll
            for (int mt = 0; mt < 2; mt++) {
                sA[mt] = make_float4(0.f, 0.f, 0.f, 0.f);
                sB[mt] = make_float4(0.f, 0.f, 0.f, 0.f);
            }
            #pragma unroll
            for (int d = 0; d < 4; d++) {
                uint32_t kf[4];
                ldsm4(kf, smem_u32(KK + (nt2*16 + krow_off) * PD + d*16 + kcol_off));
                #pragma unroll
                for (int mt = 0; mt < 2; mt++) {
                    mma16816(sA[mt], Qhi[mt][d], kf);
                    mma16816(sB[mt], Qhi[mt][d], kf + 2);
                }
            }
            float ma = mt_[nt2*16 + cc2],     mb = mt_[nt2*16 + cc2 + 1];
            float mc = mt_[nt2*16 + 8 + cc2], md = mt_[nt2*16 + 8 + cc2 + 1];
            #pragma unroll
            for (int mt = 0; mt < 2; mt++) {
                rs[mt][0] += ma * ex2(sA[mt].x) + mb * ex2(sA[mt].y)
                           + mc * ex2(sB[mt].x) + md * ex2(sB[mt].y);
                rs[mt][1] += ma * ex2(sA[mt].z) + mb * ex2(sA[mt].w)
                           + mc * ex2(sB[mt].z) + md * ex2(sB[mt].w);
            }
        }
    }
    float inv0[2], inv1[2];
    #pragma unroll
    for (int mt = 0; mt < 2; mt++) {
        float a0 = rs[mt][0], a1 = rs[mt][1];
        a0 += __shfl_xor_sync(0xffffffffu, a0, 1);
        a0 += __shfl_xor_sync(0xffffffffu, a0, 2);
        a1 += __shfl_xor_sync(0xffffffffu, a1, 1);
        a1 += __shfl_xor_sync(0xffffffffu, a1, 2);
        inv0[mt] = 1.0f / a0;
        inv1[mt] = 1.0f / a1;
    }

    // ================= Phase B: normalized attn + AV =================
    float4 o[2][8];
    #pragma unroll
    for (int mt = 0; mt < 2; mt++)
        #pragma unroll
        for (int t = 0; t < 8; t++) o[mt][t] = make_float4(0.f, 0.f, 0.f, 0.f);

    loadK(0, KB0); loadV(0, VH0); CP_COMMIT();
    for (int kb = 0; kb < 32; kb++) {
        CP_WAIT0();
        __syncthreads();
        if (kb < 31) {
            loadK(kb + 1, (kb & 1) ? KB0 : KB1);
            loadV(kb + 1, (kb & 1) ? VH0 : VH1);
            CP_COMMIT();
        }
        __half* KK  = (kb & 1) ? KB1 : KB0;
        __half* VVh = (kb & 1) ? VH1 : VH0;
        const float* mt_ = msks + kb * 64;

        uint32_t phi[2][4][4];
        #pragma unroll
        for (int nt2 = 0; nt2 < 4; nt2++) {
            float4 sA[2], sB[2];
            #pragma unroll
            for (int mt = 0; mt < 2; mt++) {
                sA[mt] = make_float4(0.f, 0.f, 0.f, 0.f);
                sB[mt] = make_float4(0.f, 0.f, 0.f, 0.f);
            }
            #pragma unroll
            for (int d = 0; d < 4; d++) {
                uint32_t kf[4];
                ldsm4(kf, smem_u32(KK + (nt2*16 + krow_off) * PD + d*16 + kcol_off));
                #pragma unroll
                for (int mt = 0; mt < 2; mt++) {
                    mma16816(sA[mt], Qhi[mt][d], kf);
                    mma16816(sB[mt], Qhi[mt][d], kf + 2);
                }
            }
            float ma = mt_[nt2*16 + cc2],     mb = mt_[nt2*16 + cc2 + 1];
            float mc = mt_[nt2*16 + 8 + cc2], md = mt_[nt2*16 + 8 + cc2 + 1];
            size_t col = (size_t)kb * 64 + nt2 * 16 + cc2;
            #pragma unroll
            for (int mt = 0; mt < 2; mt++) {
                float p0 = ma * ex2(sA[mt].x), p1 = mb * ex2(sA[mt].y);
                float p2 = ma * ex2(sA[mt].z), p3 = mb * ex2(sA[mt].w);
                float q0 = mc * ex2(sB[mt].x), q1 = md * ex2(sB[mt].y);
                float q2 = mc * ex2(sB[mt].z), q3 = md * ex2(sB[mt].w);

                int srow = s0 + wq + mt * 16 + g;
                float* r0p = &attn[((size_t)bh * S_ + srow) * S_ + col];
                float* r1p = &attn[((size_t)bh * S_ + srow + 8) * S_ + col];
                __stcs((float2*)r0p,       make_float2(p0 * inv0[mt], p1 * inv0[mt]));
                __stcs((float2*)(r0p + 8), make_float2(q0 * inv0[mt], q1 * inv0[mt]));
                __stcs((float2*)r1p,       make_float2(p2 * inv1[mt], p3 * inv1[mt]));
                __stcs((float2*)(r1p + 8), make_float2(q2 * inv1[mt], q3 * inv1[mt]));

                phi[mt][nt2][0] = cvt2(p0, p1);
                phi[mt][nt2][1] = cvt2(p2, p3);
                phi[mt][nt2][2] = cvt2(q0, q1);
                phi[mt][nt2][3] = cvt2(q2, q3);
            }
        }

        #pragma unroll
        for (int dt2 = 0; dt2 < 4; dt2++) {
            #pragma unroll
            for (int j = 0; j < 4; j++) {
                uint32_t vh[4];
                ldsm4t(vh, smem_u32(VVh + (j*16 + vrow_off) * PD + dt2*16 + vcol_off));
                #pragma unroll
                for (int mt = 0; mt < 2; mt++) {
                    mma16816(o[mt][2*dt2],     phi[mt][j], vh);
                    mma16816(o[mt][2*dt2 + 1], phi[mt][j], vh + 2);
                }
            }
        }
    }

    // ---- finalize ----
    #pragma unroll
    for (int mt = 0; mt < 2; mt++) {
        int srow = s0 + wq + mt * 16 + g;
        #pragma unroll
        for (int dt = 0; dt < 8; dt++) {
            int d = dt * 8 + cc2;
            *(float2*)&out[(((size_t)b * S_ + srow) * H_ + h) * D_ + d] =
                make_float2(o[mt][dt].x * inv0[mt], o[mt][dt].y * inv0[mt]);
            *(float2*)&out[(((size_t)b * S_ + srow + 8) * H_ + h) * D_ + d] =
                make_float2(o[mt][dt].z * inv1[mt], o[mt][dt].w * inv1[mt]);
        }
    }
}

// ---------------------------------------------------------------------------
extern "C" void kernel_launch(void* const* d_in, const int* in_sizes, int n_in,
                              void* d_out, int out_size) {
    (void)in_sizes; (void)n_in; (void)out_size;
    const float* query = (const float*)d_in[0];
    const float* key   = (const float*)d_in[1];
    const float* value = (const float*)d_in[2];
    const int*   mask  = (const int*)d_in[3];
    const float* Wq    = (const float*)d_in[4];
    const float* Wk    = (const float*)d_in[5];
    const float* Wv    = (const float*)d_in[6];

    float* out  = (float*)d_out;                        // attn_output [B,S,E]
    float* attn = out + (size_t)B_ * S_ * E_;           // attn [B,H,S,S]

    // one-shot fp32 -> fp16 conversion of X and W
    dim3 cgrid(M_ * E_ / 4 / 256, 6);
    cvt6<<<cgrid, 256>>>(query, key, value, Wq, Wk, Wv);

    int proj_smem = 15360 * (int)sizeof(__half);        // 30720 B
    cudaFuncSetAttribute(proj_mma, cudaFuncAttributeMaxDynamicSharedMemorySize, proj_smem);
    dim3 pgrid(E_ / 64, M_ / 128, 3);
    proj_mma<<<pgrid, 256, proj_smem>>>(0);

    int smem_bytes = 4 * 64 * PD * (int)sizeof(__half) + S_ * (int)sizeof(float); // 45056
    cudaFuncSetAttribute(attn_mma2, cudaFuncAttributeMaxDynamicSharedMemorySize, smem_bytes);
    attn_mma2<<<dim3(S_ / 64, B_ * H_), 64, smem_bytes>>>(mask, out, attn);
}